// round 7
// baseline (speedup 1.0000x reference)
#include <cuda_runtime.h>
#include <math.h>

#define BB 2
#define C  19
#define H  128
#define W  128
#define CH 320
#define CG 32
#define HW (H*W)
#define NBLK 256                   // total blocks (== rows == pixel blocks)
#define F32_FLUSH_THRESH 1.1754943508222875e-38   // FLT_MIN: emulate reference FTZ exp

// ---------------- scratch (__device__ globals; no allocation) ----------------
__device__ float    g_prob[BB * C * HW];    // softmax(logits)
__device__ float    g_Sd[BB * CG * CG * 5]; // per coarse cell: E,SW,S,SE sims + oob sim
__device__ double   g_acc[2];
__device__ int      g_nmask;
__device__ unsigned g_done = 0;             // finalize ticket (wraps -> replay-safe)
__device__ unsigned g_bar_count = 0;        // barrier arrivals (self-resets)
__device__ unsigned g_bar_gen   = 0;        // barrier generation (monotone, wrap-safe)

__device__ __forceinline__ void grid_barrier() {
    __syncthreads();
    if (threadIdx.x == 0) {
        unsigned gen = *(volatile unsigned*)&g_bar_gen;
        __threadfence();
        if (atomicAdd(&g_bar_count, 1u) == NBLK - 1) {
            g_bar_count = 0;
            __threadfence();
            atomicAdd(&g_bar_gen, 1u);
        } else {
            while (*(volatile unsigned*)&g_bar_gen == gen) { __nanosleep(40); }
        }
        __threadfence();
    }
    __syncthreads();
}

__global__ void __launch_bounds__(128) fused_k(const float* __restrict__ logits,
                                               const float* __restrict__ x_ema,
                                               float* __restrict__ out) {
    int blk = blockIdx.x;
    int t   = threadIdx.x;
    if (blk == 0 && t == 0) { g_acc[0] = 0.0; g_acc[1] = 0.0; g_nmask = 0; }

    // ================= Phase A: softmax over C=19, one row per block =========
    {
        int b = blk >> 7, i = blk & 127;
        const float* base = logits + (size_t)b * C * HW + i * W + t;
        float v[C];
        float m = -INFINITY;
#pragma unroll
        for (int c = 0; c < C; c++) { v[c] = base[c * HW]; m = fmaxf(m, v[c]); }
        float s = 0.f;
#pragma unroll
        for (int c = 0; c < C; c++) { v[c] = expf(v[c] - m); s += v[c]; }
        float inv = 1.f / s;
        float* o = g_prob + (size_t)b * C * HW + i * W + t;
#pragma unroll
        for (int c = 0; c < C; c++) o[c * HW] = v[c] * inv;
    }

    // ================= Phase B: directed coarse-cell sim table ===============
    // blocks < 64: one coarse row each. lanes = 32 cells (coalesced), 4 warps
    // split channels mod 4. Neighbors via shfl. Edge-lane garbage entries are
    // never read by Phase C (proved by the lookup pattern).
    grid_barrier();
    if (blk < BB * CG) {
        int b  = blk >> 5, ci = blk & 31;
        int g  = t >> 5, lane = t & 31;           // lane == cj
        const float* xb = x_ema + ((size_t)(b * CH) * CG + ci) * CG + lane;
        bool has_s = (ci < CG - 1);

        float a0 = 0.f, a1 = 0.f, a2 = 0.f, a3 = 0.f, a4 = 0.f;
#pragma unroll 4
        for (int ch = g; ch < CH; ch += 4) {
            float c  = xb[(size_t)ch * (CG * CG)];
            float sv = has_s ? xb[(size_t)ch * (CG * CG) + CG] : 0.f;
            float nE = __shfl_down_sync(0xffffffffu, c,  1);
            float sW = __shfl_up_sync  (0xffffffffu, sv, 1);
            float sE = __shfl_down_sync(0xffffffffu, sv, 1);
            float d0 = nE - c, d1 = sW - c, d2 = sv - c, d3 = sE - c;
            a0 += d0 * d0; a1 += d1 * d1; a2 += d2 * d2; a3 += d3 * d3; a4 += c * c;
        }
        __shared__ float red[4][32][5];
        red[g][lane][0] = a0; red[g][lane][1] = a1; red[g][lane][2] = a2;
        red[g][lane][3] = a3; red[g][lane][4] = a4;
        __syncthreads();
        {
            // 128 threads cover entries e=0..3 (one per warp); warp 0's lanes
            // ALSO write e=4 (oob sim). (R6 bug: e=4 was never written.)
            int cj = t & 31, e = t >> 5;
            float* cell_out = g_Sd + (size_t)((b * CG + ci) * CG + cj) * 5;
            float s = red[0][cj][e] + red[1][cj][e] + red[2][cj][e] + red[3][cj][e];
            double tt = exp(-(double)s * 0.25);      // FTZ-immune double exp
            if (tt < F32_FLUSH_THRESH) tt = 0.0;     // emulate reference FTZ
            cell_out[e] = (float)tt;
            if (e == 0) {
                float s4 = red[0][cj][4] + red[1][cj][4] + red[2][cj][4] + red[3][cj][4];
                double t4 = exp(-(double)s4 * 0.25);
                if (t4 < F32_FLUSH_THRESH) t4 = 0.0;
                cell_out[4] = (float)t4;
            }
        }
    }

    // ================= Phase C: per-pixel loss + finalize ====================
    grid_barrier();
    {
        int b = blk >> 7, i = blk & 127;
        int j = t;

        const float* P = g_prob + (size_t)b * C * HW;
        float p[C];
        float sum_p = 0.f;
        {
            const float* pc = P + i * W + j;
#pragma unroll
            for (int c = 0; c < C; c++) { p[c] = pc[c * HW]; sum_p += p[c]; }
        }

        int ci = i >> 2, cj = j >> 2;
        const float* Sb = g_Sd + (size_t)b * CG * CG * 5;
        float sim_oob = Sb[(ci * CG + cj) * 5 + 4];

        float sim[9], cp[9], cn[9];
#pragma unroll
        for (int k = 0; k < 9; k++) {
            int a  = k / 3, b2 = k % 3;
            int ni = i + (a - 1) * 2;
            int nj = j + (b2 - 1) * 2;
            if (ni < 0 || ni >= H || nj < 0 || nj >= W) {
                sim[k] = sim_oob; cp[k] = 0.f; cn[k] = 0.f;
            } else {
                const float* Q = P + ni * W + nj;
                float cpos = 0.f, sq = 0.f;
#pragma unroll
                for (int c = 0; c < C; c++) { float q = Q[c * HW]; cpos += p[c] * q; sq += q; }
                cp[k] = cpos;
                cn[k] = sum_p * sq - cpos;
                int dci = (ni >> 2) - ci;
                int dcj = (nj >> 2) - cj;
                float sv;
                if ((dci | dcj) == 0)      sv = 1.0f;
                else if (dci < 0)          sv = Sb[((ci - 1) * CG + cj + dcj) * 5 + (2 - dcj)];
                else if (dci > 0)          sv = Sb[(ci * CG + cj) * 5 + (2 + dcj)];
                else if (dcj > 0)          sv = Sb[(ci * CG + cj) * 5 + 0];
                else                       sv = Sb[(ci * CG + cj - 1) * 5 + 0];
                sim[k] = sv;
            }
        }

        // top-5 largest sims (stable: lowest index wins ties, like jax top_k)
        float lpos = 0.f;
        {
            bool used[9];
#pragma unroll
            for (int k = 0; k < 9; k++) used[k] = false;
#pragma unroll
            for (int tt = 0; tt < 5; tt++) {
                float bv = -1.f, bcp = 0.f; int sel = -1;
#pragma unroll
                for (int k = 0; k < 9; k++)
                    if (!used[k] && sim[k] > bv) { bv = sim[k]; bcp = cp[k]; sel = k; }
#pragma unroll
                for (int k = 0; k < 9; k++) used[k] = used[k] || (k == sel);
                lpos += bv * (-bcp);
            }
        }
        // bottom-4 sims (stable lowest-index ties, like top_k(-sim))
        float lneg = 0.f;
        {
            bool used[9];
#pragma unroll
            for (int k = 0; k < 9; k++) used[k] = false;
#pragma unroll
            for (int tt = 0; tt < 4; tt++) {
                float bv = 2.f, bcn = 0.f; int sel = -1;
#pragma unroll
                for (int k = 0; k < 9; k++)
                    if (!used[k] && sim[k] < bv) { bv = sim[k]; bcn = cn[k]; sel = k; }
#pragma unroll
                for (int k = 0; k < 9; k++) used[k] = used[k] || (k == sel);
                lneg += (1.f - bv) * (-bcn);
            }
        }

        bool msk = x_ema[(size_t)b * CH * CG * CG + ci * CG + cj] > 0.f;
        float mlp = msk ? lpos : 0.f;
        float mln = msk ? lneg : 0.f;
        int   mc  = msk ? 1 : 0;

        __shared__ float s0[4], s1[4];
        __shared__ int   s2[4];
#pragma unroll
        for (int off = 16; off; off >>= 1) {
            mlp += __shfl_down_sync(0xffffffffu, mlp, off);
            mln += __shfl_down_sync(0xffffffffu, mln, off);
            mc  += __shfl_down_sync(0xffffffffu, mc,  off);
        }
        int lane = t & 31, wid = t >> 5;
        if (lane == 0) { s0[wid] = mlp; s1[wid] = mln; s2[wid] = mc; }
        __syncthreads();
        if (t == 0) {
            double a0 = (double)s0[0] + s0[1] + s0[2] + s0[3];
            double a1 = (double)s1[0] + s1[1] + s1[2] + s1[3];
            int    a2 = s2[0] + s2[1] + s2[2] + s2[3];
            atomicAdd(&g_acc[0], a0);
            atomicAdd(&g_acc[1], a1);
            atomicAdd(&g_nmask, a2);
            __threadfence();
            unsigned old = atomicInc(&g_done, NBLK - 1);   // wraps to 0 -> replay-safe
            if (old == NBLK - 1) {
                double p0 = atomicAdd(&g_acc[0], 0.0);
                double p1 = atomicAdd(&g_acc[1], 0.0);
                int    nm = atomicAdd(&g_nmask, 0);
                out[0] = (float)p0 / ((float)nm * 5.0f);   // W_POS = 1
                out[1] = (float)p1 / ((float)nm * 4.0f);   // W_NEG = 1
            }
        }
    }
}

// ---------------- launch ----------------
extern "C" void kernel_launch(void* const* d_in, const int* in_sizes, int n_in,
                              void* d_out, int out_size) {
    const float* logits = (const float*)d_in[0];  // (2,19,128,128)
    const float* x_ema  = (const float*)d_in[1];  // (2,320,32,32)
    // d_in[2] = img_trg, unused by the reference.
    float* out = (float*)d_out;

    fused_k<<<NBLK, 128>>>(logits, x_ema, out);
}

// round 8
// speedup vs baseline: 1.2965x; 1.2965x over previous
#include <cuda_runtime.h>
#include <math.h>

#define BB 2
#define C  19
#define H  128
#define W  128
#define CH 320
#define CG 32
#define HW (H*W)
#define NPIX_BLK 256               // softmax / pixel blocks (one image row each)
#define NSIM_BLK (BB*CG)           // 64 simtab blocks (one coarse row each)
#define F32_FLUSH_THRESH 1.1754943508222875e-38   // FLT_MIN: emulate reference FTZ exp

// ---------------- scratch (__device__ globals; no allocation) ----------------
__device__ float    g_prob[BB * C * HW];    // softmax(logits)
__device__ float    g_Sd[BB * CG * CG * 5]; // per coarse cell: E,SW,S,SE sims + oob sim
__device__ double   g_acc[2];
__device__ int      g_nmask;
__device__ unsigned g_done = 0;             // finalize ticket (wraps -> replay-safe)

// ======== kernel 1: softmax (blocks 0..255) || directed sim table (256..319) ========
__global__ void __launch_bounds__(128) pre_k(const float* __restrict__ logits,
                                             const float* __restrict__ x_ema) {
    int blk = blockIdx.x;
    int t   = threadIdx.x;
    if (blk == 0 && t == 0) { g_acc[0] = 0.0; g_acc[1] = 0.0; g_nmask = 0; }

    if (blk < NPIX_BLK) {
        // ---- softmax over C=19 for one image row ----
        int b = blk >> 7, i = blk & 127;
        const float* base = logits + (size_t)b * C * HW + i * W + t;
        float v[C];
        float m = -INFINITY;
#pragma unroll
        for (int c = 0; c < C; c++) { v[c] = base[c * HW]; m = fmaxf(m, v[c]); }
        float s = 0.f;
#pragma unroll
        for (int c = 0; c < C; c++) { v[c] = expf(v[c] - m); s += v[c]; }
        float inv = 1.f / s;
        float* o = g_prob + (size_t)b * C * HW + i * W + t;
#pragma unroll
        for (int c = 0; c < C; c++) o[c * HW] = v[c] * inv;
    } else {
        // ---- directed coarse-cell sim table, one coarse row per block ----
        // lanes = 32 cells (coalesced); 4 warps split channels mod 4.
        // Neighbors via shfl; edge-lane garbage entries are never read by pixel_k.
        int cb = blk - NPIX_BLK;
        int b  = cb >> 5, ci = cb & 31;
        int g  = t >> 5, lane = t & 31;           // lane == cj
        const float* xb = x_ema + ((size_t)(b * CH) * CG + ci) * CG + lane;
        bool has_s = (ci < CG - 1);

        float a0 = 0.f, a1 = 0.f, a2 = 0.f, a3 = 0.f, a4 = 0.f;
#pragma unroll 4
        for (int ch = g; ch < CH; ch += 4) {
            float c  = xb[(size_t)ch * (CG * CG)];
            float sv = has_s ? xb[(size_t)ch * (CG * CG) + CG] : 0.f;
            float nE = __shfl_down_sync(0xffffffffu, c,  1);
            float sW = __shfl_up_sync  (0xffffffffu, sv, 1);
            float sE = __shfl_down_sync(0xffffffffu, sv, 1);
            float d0 = nE - c, d1 = sW - c, d2 = sv - c, d3 = sE - c;
            a0 += d0 * d0; a1 += d1 * d1; a2 += d2 * d2; a3 += d3 * d3; a4 += c * c;
        }
        __shared__ float red[4][32][5];
        red[g][lane][0] = a0; red[g][lane][1] = a1; red[g][lane][2] = a2;
        red[g][lane][3] = a3; red[g][lane][4] = a4;
        __syncthreads();
        {
            // 128 threads cover e=0..3 (one per warp); warp 0 also writes e=4.
            int cj = t & 31, e = t >> 5;
            float* cell_out = g_Sd + (size_t)((b * CG + ci) * CG + cj) * 5;
            float s = red[0][cj][e] + red[1][cj][e] + red[2][cj][e] + red[3][cj][e];
            double tt = exp(-(double)s * 0.25);      // FTZ-immune double exp
            if (tt < F32_FLUSH_THRESH) tt = 0.0;     // emulate reference FTZ
            cell_out[e] = (float)tt;
            if (e == 0) {
                float s4 = red[0][cj][4] + red[1][cj][4] + red[2][cj][4] + red[3][cj][4];
                double t4 = exp(-(double)s4 * 0.25);
                if (t4 < F32_FLUSH_THRESH) t4 = 0.0;
                cell_out[4] = (float)t4;
            }
        }
    }
}

// ======== kernel 2: per-pixel loss + fused finalize ========
__global__ void __launch_bounds__(128) pixel_k(const float* __restrict__ x_ema,
                                               float* __restrict__ out) {
    int blk = blockIdx.x;
    int t   = threadIdx.x;
    int b = blk >> 7, i = blk & 127;
    int j = t;

    const float* P = g_prob + (size_t)b * C * HW;
    float p[C];
    float sum_p = 0.f;
    {
        const float* pc = P + i * W + j;
#pragma unroll
        for (int c = 0; c < C; c++) { p[c] = pc[c * HW]; sum_p += p[c]; }
    }

    int ci = i >> 2, cj = j >> 2;
    const float* Sb = g_Sd + (size_t)b * CG * CG * 5;
    float sim_oob = Sb[(ci * CG + cj) * 5 + 4];

    float sim[9], cp[9], cn[9];
#pragma unroll
    for (int k = 0; k < 9; k++) {
        int a  = k / 3, b2 = k % 3;
        int ni = i + (a - 1) * 2;
        int nj = j + (b2 - 1) * 2;
        if (ni < 0 || ni >= H || nj < 0 || nj >= W) {
            sim[k] = sim_oob; cp[k] = 0.f; cn[k] = 0.f;
        } else {
            const float* Q = P + ni * W + nj;
            float cpos = 0.f, sq = 0.f;
#pragma unroll
            for (int c = 0; c < C; c++) { float q = Q[c * HW]; cpos += p[c] * q; sq += q; }
            cp[k] = cpos;
            cn[k] = sum_p * sq - cpos;
            int dci = (ni >> 2) - ci;
            int dcj = (nj >> 2) - cj;
            float sv;
            if ((dci | dcj) == 0)      sv = 1.0f;
            else if (dci < 0)          sv = Sb[((ci - 1) * CG + cj + dcj) * 5 + (2 - dcj)];
            else if (dci > 0)          sv = Sb[(ci * CG + cj) * 5 + (2 + dcj)];
            else if (dcj > 0)          sv = Sb[(ci * CG + cj) * 5 + 0];
            else                       sv = Sb[(ci * CG + cj - 1) * 5 + 0];
            sim[k] = sv;
        }
    }

    // top-5 largest sims (stable: lowest index wins ties, like jax top_k)
    float lpos = 0.f;
    {
        bool used[9];
#pragma unroll
        for (int k = 0; k < 9; k++) used[k] = false;
#pragma unroll
        for (int tt = 0; tt < 5; tt++) {
            float bv = -1.f, bcp = 0.f; int sel = -1;
#pragma unroll
            for (int k = 0; k < 9; k++)
                if (!used[k] && sim[k] > bv) { bv = sim[k]; bcp = cp[k]; sel = k; }
#pragma unroll
            for (int k = 0; k < 9; k++) used[k] = used[k] || (k == sel);
            lpos += bv * (-bcp);
        }
    }
    // bottom-4 sims (stable lowest-index ties, like top_k(-sim))
    float lneg = 0.f;
    {
        bool used[9];
#pragma unroll
        for (int k = 0; k < 9; k++) used[k] = false;
#pragma unroll
        for (int tt = 0; tt < 4; tt++) {
            float bv = 2.f, bcn = 0.f; int sel = -1;
#pragma unroll
            for (int k = 0; k < 9; k++)
                if (!used[k] && sim[k] < bv) { bv = sim[k]; bcn = cn[k]; sel = k; }
#pragma unroll
            for (int k = 0; k < 9; k++) used[k] = used[k] || (k == sel);
            lneg += (1.f - bv) * (-bcn);
        }
    }

    bool msk = x_ema[(size_t)b * CH * CG * CG + ci * CG + cj] > 0.f;
    float mlp = msk ? lpos : 0.f;
    float mln = msk ? lneg : 0.f;
    int   mc  = msk ? 1 : 0;

    __shared__ float s0[4], s1[4];
    __shared__ int   s2[4];
#pragma unroll
    for (int off = 16; off; off >>= 1) {
        mlp += __shfl_down_sync(0xffffffffu, mlp, off);
        mln += __shfl_down_sync(0xffffffffu, mln, off);
        mc  += __shfl_down_sync(0xffffffffu, mc,  off);
    }
    int lane = t & 31, wid = t >> 5;
    if (lane == 0) { s0[wid] = mlp; s1[wid] = mln; s2[wid] = mc; }
    __syncthreads();
    if (t == 0) {
        double a0 = (double)s0[0] + s0[1] + s0[2] + s0[3];
        double a1 = (double)s1[0] + s1[1] + s1[2] + s1[3];
        int    a2 = s2[0] + s2[1] + s2[2] + s2[3];
        atomicAdd(&g_acc[0], a0);
        atomicAdd(&g_acc[1], a1);
        atomicAdd(&g_nmask, a2);
        __threadfence();
        unsigned old = atomicInc(&g_done, NPIX_BLK - 1);   // wraps to 0 -> replay-safe
        if (old == NPIX_BLK - 1) {
            double p0 = atomicAdd(&g_acc[0], 0.0);
            double p1 = atomicAdd(&g_acc[1], 0.0);
            int    nm = atomicAdd(&g_nmask, 0);
            out[0] = (float)p0 / ((float)nm * 5.0f);   // W_POS = 1
            out[1] = (float)p1 / ((float)nm * 4.0f);   // W_NEG = 1
        }
    }
}

// ---------------- launch ----------------
extern "C" void kernel_launch(void* const* d_in, const int* in_sizes, int n_in,
                              void* d_out, int out_size) {
    const float* logits = (const float*)d_in[0];  // (2,19,128,128)
    const float* x_ema  = (const float*)d_in[1];  // (2,320,32,32)
    // d_in[2] = img_trg, unused by the reference.
    float* out = (float*)d_out;

    pre_k<<<NPIX_BLK + NSIM_BLK, 128>>>(logits, x_ema);
    pixel_k<<<NPIX_BLK, 128>>>(x_ema, out);
}